// round 15
// baseline (speedup 1.0000x reference)
#include <cuda_runtime.h>
#include <cstdint>

// Problem shape (fixed by the reference)
#define BATCH 64
#define SEQ   8
#define VOCAB 128000

// 10 splits/row -> 640 blocks x 256 threads (8 warps).
// Split = 12800 floats = 3200 float4 -> 12 f4/thread + 128-f4 remainder.
#define SPLITS       10
#define THREADS      256
#define SPLIT_FLOATS (VOCAB / SPLITS)        // 12800
#define SPLIT_F4     (SPLIT_FLOATS / 4)      // 3200
#define BW_          4                        // f4 per pipeline batch

// Scratch (no cudaMalloc allowed). g_count starts 0, reset by last arriver
// each run -> deterministic across graph replays.
__device__ float g_pmax[BATCH * SPLITS];
__device__ int   g_pidx[BATCH * SPLITS];
__device__ int   g_count[BATCH];

__device__ __forceinline__ void take_better(float v, int i, float& bm, int& bi) {
    // full tie-break (first occurrence = smaller index) for cross-thread merge
    if (v > bm || (v == bm && i < bi)) { bm = v; bi = i; }
}

// In-thread scan: this thread's indices strictly increase -> strict > keeps
// first occurrence. fmaxf tree for ILP; index recovered on rare update.
__device__ __forceinline__ void proc(float4 v, int e, float& bm, int& bi) {
    float m = fmaxf(fmaxf(v.x, v.y), fmaxf(v.z, v.w));
    if (m > bm) {
        bm = m;
        bi = (m == v.x) ? e : (m == v.y) ? e + 1 : (m == v.z) ? e + 2 : e + 3;
    }
}

__global__ __launch_bounds__(THREADS, 5) void argmax_pipe(
    const float* __restrict__ logits, float* __restrict__ out)
{
    const int row   = blockIdx.x / SPLITS;   // 0..63
    const int split = blockIdx.x % SPLITS;   // 0..9

    const float4* __restrict__ p = reinterpret_cast<const float4*>(
        logits + (size_t)row * (SEQ * VOCAB) + (size_t)(SEQ - 1) * VOCAB
               + (size_t)split * SPLIT_FLOATS);

    const int tid = threadIdx.x;
    const int idx_base = split * SPLIT_FLOATS;

    float bm = -__int_as_float(0x7f800000);  // -inf
    int   bi = 0x7fffffff;

    // Software-pipelined double buffer: batches of 4 f4; while processing one
    // batch the next batch's loads are in flight -> 4-8 LDG.128 outstanding
    // per thread throughout the load phase.
    float4 b0[BW_], b1[BW_];

    #pragma unroll
    for (int u = 0; u < BW_; ++u) b0[u] = p[tid + u * THREADS];             // batch 0

    #pragma unroll
    for (int u = 0; u < BW_; ++u) b1[u] = p[tid + (BW_ + u) * THREADS];     // batch 1
    #pragma unroll
    for (int u = 0; u < BW_; ++u)
        proc(b0[u], idx_base + (tid + u * THREADS) * 4, bm, bi);

    #pragma unroll
    for (int u = 0; u < BW_; ++u) b0[u] = p[tid + (2 * BW_ + u) * THREADS]; // batch 2
    #pragma unroll
    for (int u = 0; u < BW_; ++u)
        proc(b1[u], idx_base + (tid + (BW_ + u) * THREADS) * 4, bm, bi);

    #pragma unroll
    for (int u = 0; u < BW_; ++u)
        proc(b0[u], idx_base + (tid + (2 * BW_ + u) * THREADS) * 4, bm, bi);

    // remainder: 3200 - 12*256 = 128 f4, first 128 threads take one each
    if (tid < SPLIT_F4 - 3 * BW_ * THREADS) {
        float4 v = p[tid + 3 * BW_ * THREADS];
        proc(v, idx_base + (tid + 3 * BW_ * THREADS) * 4, bm, bi);
    }

    // intra-warp reduce (full tie-break)
    #pragma unroll
    for (int off = 16; off > 0; off >>= 1) {
        float om = __shfl_down_sync(0xffffffffu, bm, off);
        int   oi = __shfl_down_sync(0xffffffffu, bi, off);
        take_better(om, oi, bm, bi);
    }

    __shared__ float sm[THREADS / 32];  // 8 warps
    __shared__ int   si[THREADS / 32];
    const int lane = tid & 31, warp = tid >> 5;
    if (lane == 0) { sm[warp] = bm; si[warp] = bi; }
    __syncthreads();

    if (warp == 0) {
        bm = (lane < THREADS / 32) ? sm[lane] : -__int_as_float(0x7f800000);
        bi = (lane < THREADS / 32) ? si[lane] : 0x7fffffff;
        #pragma unroll
        for (int off = 4; off > 0; off >>= 1) {
            float om = __shfl_down_sync(0xffffffffu, bm, off);
            int   oi = __shfl_down_sync(0xffffffffu, bi, off);
            take_better(om, oi, bm, bi);
        }
        if (lane == 0) {
            // publish this split's partial
            g_pmax[row * SPLITS + split] = bm;
            g_pidx[row * SPLITS + split] = bi;
            __threadfence();
            int old = atomicAdd(&g_count[row], 1);
            if (old == SPLITS - 1) {
                // last arriver merges (ascending split order: strict > keeps
                // first occurrence on exact ties)
                volatile float* vm = g_pmax + row * SPLITS;
                volatile int*   vi = g_pidx + row * SPLITS;
                float fm = vm[0];
                int   fi = vi[0];
                #pragma unroll
                for (int s = 1; s < SPLITS; ++s) {
                    float v = vm[s];
                    int   i = vi[s];
                    if (v > fm) { fm = v; fi = i; }
                }
                out[row] = (float)fi;   // harness compares as float32
                g_count[row] = 0;       // reset for next graph replay
            }
        }
    }
}

extern "C" void kernel_launch(void* const* d_in, const int* in_sizes, int n_in,
                              void* d_out, int out_size) {
    const float* logits = (const float*)d_in[0];
    argmax_pipe<<<BATCH * SPLITS, THREADS>>>(logits, (float*)d_out);
}